// round 12
// baseline (speedup 1.0000x reference)
#include <cuda_runtime.h>
#include <cuda_bf16.h>
#include <cstdint>

// QFNetBlock: normalize -> 4 complex GEMM layers (CNOT perm after 0,2) -> abs.
// Warp-specialized complex GEMM: warps 0-3 = pure consumers (ldm+MMA only),
// warp 4 = producer (cp.async S ring + U prefetch/cvt/STS). State carried as
// pre-split bf16 hi/lo arrays. CTA 64x64, warp tile 32x32, 2 CTAs/SM.

#define DD 4096
#define BB 256
#define NW 12
#define PKN (BB * DD)

#define KC 16
#define NCHUNK (DD / KC)   // 256
#define SROW 24            // bf16 per smem row (48 B)
#define SROWB 48

// byte offsets of tiles within one stage (4 tiles x 64 rows x 48B)
#define TB_H0 0
#define TB_L0 3072
#define TB_H1 6144
#define TB_L1 9216
#define STAGE_BYTES 12288
#define U_BASE (3 * STAGE_BYTES)              // S ring: 3 stages
#define SMEM_BYTES (U_BASE + 2 * STAGE_BYTES) // + U ring: 2 stages = 61440 B

// Packed state: 2 ping-pong buffers x 4 arrays (rH, rL, iH, iL) x PKN bf16.
__device__ __nv_bfloat16 g_pk[2 * 4 * PKN];

__device__ __forceinline__ uint32_t smem_u32(const void* p) {
    uint32_t a;
    asm("{ .reg .u64 t; cvta.to.shared.u64 t, %1; cvt.u32.u64 %0, t; }" : "=r"(a) : "l"(p));
    return a;
}

__device__ __forceinline__ void cvt_hilo2(float a, float b, uint32_t& hi, uint32_t& lo) {
    __nv_bfloat16 ha = __float2bfloat16_rn(a);
    __nv_bfloat16 hb = __float2bfloat16_rn(b);
    __nv_bfloat16 la = __float2bfloat16_rn(a - __bfloat162float(ha));
    __nv_bfloat16 lb = __float2bfloat16_rn(b - __bfloat162float(hb));
    __nv_bfloat162 h2 = __halves2bfloat162(ha, hb);
    __nv_bfloat162 l2 = __halves2bfloat162(la, lb);
    hi = *reinterpret_cast<uint32_t*>(&h2);
    lo = *reinterpret_cast<uint32_t*>(&l2);
}

__device__ __forceinline__ void ldm4(uint32_t* r, uint32_t addr) {
    asm volatile("ldmatrix.sync.aligned.m8n8.x4.shared.b16 {%0,%1,%2,%3}, [%4];"
                 : "=r"(r[0]), "=r"(r[1]), "=r"(r[2]), "=r"(r[3]) : "r"(addr));
}

__device__ __forceinline__ void cpasync16(uint32_t dst, const void* src) {
    asm volatile("cp.async.ca.shared.global [%0], [%1], 16;" :: "r"(dst), "l"(src));
}
#define CP_COMMIT() asm volatile("cp.async.commit_group;" ::: "memory")
#define CP_WAIT0()  asm volatile("cp.async.wait_group 0;" ::: "memory")
#define CP_WAIT1()  asm volatile("cp.async.wait_group 1;" ::: "memory")

#define MMA(C, A, B)                                                           \
    asm volatile(                                                              \
        "mma.sync.aligned.m16n8k16.row.col.f32.bf16.bf16.f32 "                 \
        "{%0,%1,%2,%3}, {%4,%5,%6,%7}, {%8,%9}, {%0,%1,%2,%3};"                \
        : "+f"((C)[0]), "+f"((C)[1]), "+f"((C)[2]), "+f"((C)[3])               \
        : "r"((A)[0]), "r"((A)[1]), "r"((A)[2]), "r"((A)[3]),                  \
          "r"((B)[0]), "r"((B)[1]))

// ---------------------------------------------------------------------------
// Complex GEMM: O[b,i] = sum_k U[i,k] * S[b,k]
// warps 0-3: consumers (2x2, warp tile 32x32). warp 4: producer.
// grid (64,4)=256 CTAs, 160 threads, 2 CTAs/SM.
// ---------------------------------------------------------------------------
template <bool CPLX>
__global__ void __launch_bounds__(160, 2)
cgemm_mma(const float* __restrict__ Ur, const float* __restrict__ Ui,
          const __nv_bfloat16* __restrict__ S, __nv_bfloat16* __restrict__ O) {
    extern __shared__ __align__(16) __nv_bfloat16 sm[];
    char* smc = reinterpret_cast<char*>(sm);

    const int tid = threadIdx.x;
    const int wid = tid >> 5;
    const int lane = tid & 31;
    const int ibase = blockIdx.x * 64;
    const int bbase = blockIdx.y * 64;
    const uint32_t smbase = smem_u32(sm);

    const __nv_bfloat16* gSrH = S;
    const __nv_bfloat16* gSrL = S + PKN;
    const __nv_bfloat16* gSiH = S + 2 * PKN;
    const __nv_bfloat16* gSiL = S + 3 * PKN;
    __nv_bfloat16* gOrH = O;
    __nv_bfloat16* gOrL = O + PKN;
    __nv_bfloat16* gOiH = O + 2 * PKN;
    __nv_bfloat16* gOiL = O + 3 * PKN;

    if (wid == 4) {
        // ===================== PRODUCER WARP =====================
        const float* pUr0 = Ur + (size_t)(ibase + lane) * DD;
        const float* pUr1 = Ur + (size_t)(ibase + lane + 32) * DD;
        const float* pUi0 = Ui + (size_t)(ibase + lane) * DD;
        const float* pUi1 = Ui + (size_t)(ibase + lane + 32) * DD;

        // S cp.asyncs: lane handles rows lane, lane+32; 2x16B per row per array
        auto stageS = [&](int st, int kbase) {
            const uint32_t dbase = smbase + st * STAGE_BYTES;
#pragma unroll
            for (int rr = 0; rr < 2; ++rr) {
                const int row = lane + rr * 32;
                const size_t g = (size_t)(bbase + row) * DD + kbase;
                const uint32_t d = dbase + row * SROWB;
                cpasync16(d + TB_H0, gSrH + g);
                cpasync16(d + TB_H0 + 16, gSrH + g + 8);
                cpasync16(d + TB_L0, gSrL + g);
                cpasync16(d + TB_L0 + 16, gSrL + g + 8);
                if (CPLX) {
                    cpasync16(d + TB_H1, gSiH + g);
                    cpasync16(d + TB_H1 + 16, gSiH + g + 8);
                    cpasync16(d + TB_L1, gSiL + g);
                    cpasync16(d + TB_L1 + 16, gSiL + g + 8);
                }
            }
        };
        // U prefetch: vv[mat*8 + rr*4 + q]
        float4 vv[16];
        auto prefU = [&](int off) {
#pragma unroll
            for (int q = 0; q < 4; ++q) {
                vv[0 + q]  = *reinterpret_cast<const float4*>(pUr0 + off + q * 4);
                vv[4 + q]  = *reinterpret_cast<const float4*>(pUr1 + off + q * 4);
                vv[8 + q]  = *reinterpret_cast<const float4*>(pUi0 + off + q * 4);
                vv[12 + q] = *reinterpret_cast<const float4*>(pUi1 + off + q * 4);
            }
        };
        auto stageU = [&](int buf) {
            char* B = smc + U_BASE + buf * STAGE_BYTES;
#pragma unroll
            for (int mat = 0; mat < 2; ++mat) {
                const int tbh = mat ? TB_H1 : TB_H0;
                const int tbl = mat ? TB_L1 : TB_L0;
#pragma unroll
                for (int rr = 0; rr < 2; ++rr) {
                    const int ro = (lane + rr * 32) * SROWB;
#pragma unroll
                    for (int q = 0; q < 4; ++q) {
                        float4 x = vv[mat * 8 + rr * 4 + q];
                        uint32_t h0, l0, h1, l1;
                        cvt_hilo2(x.x, x.y, h0, l0);
                        cvt_hilo2(x.z, x.w, h1, l1);
                        *reinterpret_cast<uint2*>(B + tbh + ro + q * 8) = make_uint2(h0, h1);
                        *reinterpret_cast<uint2*>(B + tbl + ro + q * 8) = make_uint2(l0, l1);
                    }
                }
            }
        };

        // prologue: S chunks 0,1 in flight; U chunk 0 staged; U chunk 1 in regs
        stageS(0, 0);
        CP_COMMIT();
        stageS(1, KC);
        CP_COMMIT();
        prefU(0);
        stageU(0);
        prefU(KC);
        CP_WAIT1();   // S0 complete; S1 may remain in flight
        __syncthreads();

        int s2 = 2;  // ring stage receiving chunk c+2
#pragma unroll 1
        for (int c = 0; c < NCHUNK; ++c) {
            if (c + 2 < NCHUNK) stageS(s2, (c + 2) * KC);
            CP_COMMIT();  // always commit: exact wait_group ledger
            if (c + 1 < NCHUNK) stageU((c + 1) & 1);
            if (c + 2 < NCHUNK) prefU((c + 2) * KC);
            CP_WAIT1();   // chunk c+1's S group drained; c+2's may fly
            __syncthreads();
            if (++s2 == 3) s2 = 0;
        }
        return;  // producer does no epilogue
    }

    // ===================== CONSUMER WARPS (0-3) =====================
    const int warp_m = wid & 1;
    const int warp_n = wid >> 1;
    const int lrow = lane >> 2;
    const int lcol2 = (lane & 3) << 1;

    const uint32_t aLane = (uint32_t)((lane & 15) * SROWB + (lane >> 4) * 16);
    const uint32_t bLane = (uint32_t)((((lane >> 4) << 3) + (lane & 7)) * SROWB +
                                      ((lane >> 3) & 1) * 16);
    const uint32_t aOff = aLane + (uint32_t)(warp_m * 32 * SROWB);

    float cR[2][4][4], cI[2][4][4];
#pragma unroll
    for (int m = 0; m < 2; ++m)
#pragma unroll
        for (int n = 0; n < 4; ++n)
#pragma unroll
            for (int r = 0; r < 4; ++r) { cR[m][n][r] = 0.f; cI[m][n][r] = 0.f; }

    __syncthreads();  // matches producer's prologue sync

    int s_stage = 0;
#pragma unroll 1
    for (int c = 0; c < NCHUNK; ++c) {
        const uint32_t base_s = smbase + (uint32_t)(s_stage * STAGE_BYTES);
        const uint32_t base_u = smbase + (uint32_t)(U_BASE + (c & 1) * STAGE_BYTES);

        // fragments for chunk c
        uint32_t aSrH[2][4], aSrL[2][4], aSiH[2][4], aSiL[2][4];
#pragma unroll
        for (int m = 0; m < 2; ++m) {
            const uint32_t am = base_s + aOff + (uint32_t)(m * 16 * SROWB);
            ldm4(aSrH[m], am + TB_H0);
            ldm4(aSrL[m], am + TB_L0);
            if (CPLX) {
                ldm4(aSiH[m], am + TB_H1);
                ldm4(aSiL[m], am + TB_L1);
            }
        }
        uint32_t bUrH[2][4], bUrL[2][4], bUiH[2][4], bUiL[2][4];
#pragma unroll
        for (int np = 0; np < 2; ++np) {
            const uint32_t bm = base_u + bLane + (uint32_t)((warp_n * 32 + np * 16) * SROWB);
            ldm4(bUrH[np], bm + TB_H0);
            ldm4(bUrL[np], bm + TB_L0);
            ldm4(bUiH[np], bm + TB_H1);
            ldm4(bUiL[np], bm + TB_L1);
        }

        // MMA burst (identical order to R10 champion)
#pragma unroll
        for (int m = 0; m < 2; ++m) {
            uint32_t aSiHn[4], aSiLn[4];
            if (CPLX) {
#pragma unroll
                for (int r = 0; r < 4; ++r) {
                    aSiHn[r] = aSiH[m][r] ^ 0x80008000u;
                    aSiLn[r] = aSiL[m][r] ^ 0x80008000u;
                }
            }
#pragma unroll
            for (int np = 0; np < 2; ++np) {
                const int n0 = np * 2, n1 = np * 2 + 1;
                MMA(cR[m][n0], aSrH[m], bUrH[np] + 0);
                MMA(cR[m][n0], aSrL[m], bUrH[np] + 0);
                MMA(cR[m][n0], aSrH[m], bUrL[np] + 0);
                MMA(cR[m][n1], aSrH[m], bUrH[np] + 2);
                MMA(cR[m][n1], aSrL[m], bUrH[np] + 2);
                MMA(cR[m][n1], aSrH[m], bUrL[np] + 2);
                MMA(cI[m][n0], aSrH[m], bUiH[np] + 0);
                MMA(cI[m][n0], aSrL[m], bUiH[np] + 0);
                MMA(cI[m][n0], aSrH[m], bUiL[np] + 0);
                MMA(cI[m][n1], aSrH[m], bUiH[np] + 2);
                MMA(cI[m][n1], aSrL[m], bUiH[np] + 2);
                MMA(cI[m][n1], aSrH[m], bUiL[np] + 2);
                if (CPLX) {
                    MMA(cR[m][n0], aSiHn, bUiH[np] + 0);
                    MMA(cR[m][n0], aSiLn, bUiH[np] + 0);
                    MMA(cR[m][n0], aSiHn, bUiL[np] + 0);
                    MMA(cR[m][n1], aSiHn, bUiH[np] + 2);
                    MMA(cR[m][n1], aSiLn, bUiH[np] + 2);
                    MMA(cR[m][n1], aSiHn, bUiL[np] + 2);
                    MMA(cI[m][n0], aSiH[m], bUrH[np] + 0);
                    MMA(cI[m][n0], aSiL[m], bUrH[np] + 0);
                    MMA(cI[m][n0], aSiH[m], bUrL[np] + 0);
                    MMA(cI[m][n1], aSiH[m], bUrH[np] + 2);
                    MMA(cI[m][n1], aSiL[m], bUrH[np] + 2);
                    MMA(cI[m][n1], aSiH[m], bUrL[np] + 2);
                }
            }
        }
        __syncthreads();
        if (++s_stage == 3) s_stage = 0;
    }

    // epilogue: hi/lo split in registers, packed bf16 global stores
#pragma unroll
    for (int m = 0; m < 2; ++m) {
#pragma unroll
        for (int n = 0; n < 4; ++n) {
            const int brow = bbase + warp_m * 32 + m * 16 + lrow;
            const int icol = ibase + warp_n * 32 + n * 8 + lcol2;
            uint32_t hi, lo;
            cvt_hilo2(cR[m][n][0], cR[m][n][1], hi, lo);
            *reinterpret_cast<uint32_t*>(gOrH + (size_t)brow * DD + icol) = hi;
            *reinterpret_cast<uint32_t*>(gOrL + (size_t)brow * DD + icol) = lo;
            cvt_hilo2(cR[m][n][2], cR[m][n][3], hi, lo);
            *reinterpret_cast<uint32_t*>(gOrH + (size_t)(brow + 8) * DD + icol) = hi;
            *reinterpret_cast<uint32_t*>(gOrL + (size_t)(brow + 8) * DD + icol) = lo;
            cvt_hilo2(cI[m][n][0], cI[m][n][1], hi, lo);
            *reinterpret_cast<uint32_t*>(gOiH + (size_t)brow * DD + icol) = hi;
            *reinterpret_cast<uint32_t*>(gOiL + (size_t)brow * DD + icol) = lo;
            cvt_hilo2(cI[m][n][2], cI[m][n][3], hi, lo);
            *reinterpret_cast<uint32_t*>(gOiH + (size_t)(brow + 8) * DD + icol) = hi;
            *reinterpret_cast<uint32_t*>(gOiL + (size_t)(brow + 8) * DD + icol) = lo;
        }
    }
}

// ---------------------------------------------------------------------------
__global__ void normalize_kernel(const float* __restrict__ x, __nv_bfloat16* __restrict__ O) {
    const int b = blockIdx.x;
    const float4* xv = reinterpret_cast<const float4*>(x + (size_t)b * DD);
    float ss = 0.f;
#pragma unroll 4
    for (int i = threadIdx.x; i < DD / 4; i += blockDim.x) {
        float4 v = xv[i];
        ss += v.x * v.x + v.y * v.y + v.z * v.z + v.w * v.w;
    }
    __shared__ float red[256];
    red[threadIdx.x] = ss;
    __syncthreads();
    for (int s = 128; s > 0; s >>= 1) {
        if (threadIdx.x < s) red[threadIdx.x] += red[threadIdx.x + s];
        __syncthreads();
    }
    const float inv = rsqrtf(red[0]);
    __nv_bfloat16* gH = O;
    __nv_bfloat16* gL = O + PKN;
    for (int i = threadIdx.x; i < DD / 4; i += blockDim.x) {
        float4 v = xv[i];
        v.x *= inv; v.y *= inv; v.z *= inv; v.w *= inv;
        uint32_t h0, l0, h1, l1;
        cvt_hilo2(v.x, v.y, h0, l0);
        cvt_hilo2(v.z, v.w, h1, l1);
        *reinterpret_cast<uint2*>(gH + (size_t)b * DD + i * 4) = make_uint2(h0, h1);
        *reinterpret_cast<uint2*>(gL + (size_t)b * DD + i * 4) = make_uint2(l0, l1);
    }
}

__global__ void perm_kernel(const __nv_bfloat16* __restrict__ in,
                            __nv_bfloat16* __restrict__ out) {
    const int idx = blockIdx.x * blockDim.x + threadIdx.x;
    const int b = idx >> 12;
    const int j = idx & (DD - 1);
    int m = j;
#pragma unroll
    for (int i = NW - 1; i >= 0; --i) {
        const int cc = NW - 1 - i;
        const int t = NW - 1 - ((i + 1) % NW);
        m ^= ((m >> cc) & 1) << t;
    }
    const size_t src = ((size_t)b << 12) + m;
    out[idx] = in[src];
    out[idx + PKN] = in[src + PKN];
    out[idx + 2 * PKN] = in[src + 2 * PKN];
    out[idx + 3 * PKN] = in[src + 3 * PKN];
}

__global__ void abs_kernel(const __nv_bfloat16* __restrict__ S, float* __restrict__ out) {
    const int idx = blockIdx.x * blockDim.x + threadIdx.x;
    const float r = __bfloat162float(S[idx]) + __bfloat162float(S[idx + PKN]);
    const float i = __bfloat162float(S[idx + 2 * PKN]) + __bfloat162float(S[idx + 3 * PKN]);
    out[idx] = sqrtf(r * r + i * i);
}

// ---------------------------------------------------------------------------
extern "C" void kernel_launch(void* const* d_in, const int* in_sizes, int n_in,
                              void* d_out, int out_size) {
    const float* x   = (const float*)d_in[0];
    const float* u0r = (const float*)d_in[1];
    const float* u0i = (const float*)d_in[2];
    const float* u1r = (const float*)d_in[3];
    const float* u1i = (const float*)d_in[4];
    const float* u2r = (const float*)d_in[5];
    const float* u2i = (const float*)d_in[6];
    const float* u3r = (const float*)d_in[7];
    const float* u3i = (const float*)d_in[8];
    float* out = (float*)d_out;

    cudaFuncSetAttribute(cgemm_mma<true>, cudaFuncAttributeMaxDynamicSharedMemorySize,
                         SMEM_BYTES);
    cudaFuncSetAttribute(cgemm_mma<false>, cudaFuncAttributeMaxDynamicSharedMemorySize,
                         SMEM_BYTES);

    __nv_bfloat16* pk;
    cudaGetSymbolAddress((void**)&pk, g_pk);
    __nv_bfloat16* pk0 = pk;
    __nv_bfloat16* pk1 = pk + 4 * PKN;

    const dim3 gg(DD / 64, BB / 64);  // (64, 4) = 256 CTAs
    const int elems = BB * DD;

    normalize_kernel<<<BB, 256>>>(x, pk0);
    cgemm_mma<false><<<gg, 160, SMEM_BYTES>>>(u0r, u0i, pk0, pk1);
    perm_kernel<<<elems / 256, 256>>>(pk1, pk0);
    cgemm_mma<true><<<gg, 160, SMEM_BYTES>>>(u1r, u1i, pk0, pk1);
    cgemm_mma<true><<<gg, 160, SMEM_BYTES>>>(u2r, u2i, pk1, pk0);
    perm_kernel<<<elems / 256, 256>>>(pk0, pk1);
    cgemm_mma<true><<<gg, 160, SMEM_BYTES>>>(u3r, u3i, pk1, pk0);
    abs_kernel<<<elems / 256, 256>>>(pk0, out);
}

// round 13
// speedup vs baseline: 1.4664x; 1.4664x over previous
#include <cuda_runtime.h>
#include <cuda_bf16.h>
#include <cstdint>

// QFNetBlock: normalize -> 4 complex GEMM layers (CNOT perm after 0,2) -> abs.
// R10 champion base (pre-split bf16 hi/lo state, cp.async 3-stage S ring,
// U register-prefetch + cvt double buffer, CTA 64x64, 2 CTAs/SM) with the
// MMA burst interleaved round-robin across accumulators to break HMMA RAW
// chains. Per-accumulator addition order unchanged -> bit-identical results.

#define DD 4096
#define BB 256
#define NW 12
#define PKN (BB * DD)

#define KC 16
#define NCHUNK (DD / KC)   // 256
#define SROW 24            // bf16 per smem row (48 B)
#define SROWB 48

// byte offsets of tiles within one S or U stage (4 tiles x 64 rows x 48B)
#define TB_H0 0
#define TB_L0 3072
#define TB_H1 6144
#define TB_L1 9216
#define STAGE_BYTES 12288
#define U_BASE (3 * STAGE_BYTES)              // S ring: 3 stages
#define SMEM_BYTES (U_BASE + 2 * STAGE_BYTES) // + U ring: 2 stages = 61440 B

// Packed state: 2 ping-pong buffers x 4 arrays (rH, rL, iH, iL) x PKN bf16.
__device__ __nv_bfloat16 g_pk[2 * 4 * PKN];

__device__ __forceinline__ uint32_t smem_u32(const void* p) {
    uint32_t a;
    asm("{ .reg .u64 t; cvta.to.shared.u64 t, %1; cvt.u32.u64 %0, t; }" : "=r"(a) : "l"(p));
    return a;
}

__device__ __forceinline__ void cvt_hilo2(float a, float b, uint32_t& hi, uint32_t& lo) {
    __nv_bfloat16 ha = __float2bfloat16_rn(a);
    __nv_bfloat16 hb = __float2bfloat16_rn(b);
    __nv_bfloat16 la = __float2bfloat16_rn(a - __bfloat162float(ha));
    __nv_bfloat16 lb = __float2bfloat16_rn(b - __bfloat162float(hb));
    __nv_bfloat162 h2 = __halves2bfloat162(ha, hb);
    __nv_bfloat162 l2 = __halves2bfloat162(la, lb);
    hi = *reinterpret_cast<uint32_t*>(&h2);
    lo = *reinterpret_cast<uint32_t*>(&l2);
}

__device__ __forceinline__ void ldm4(uint32_t* r, uint32_t addr) {
    asm volatile("ldmatrix.sync.aligned.m8n8.x4.shared.b16 {%0,%1,%2,%3}, [%4];"
                 : "=r"(r[0]), "=r"(r[1]), "=r"(r[2]), "=r"(r[3]) : "r"(addr));
}

__device__ __forceinline__ void cpasync16(uint32_t dst, const void* src) {
    asm volatile("cp.async.ca.shared.global [%0], [%1], 16;" :: "r"(dst), "l"(src));
}
#define CP_COMMIT() asm volatile("cp.async.commit_group;" ::: "memory")
#define CP_WAIT0()  asm volatile("cp.async.wait_group 0;" ::: "memory")
#define CP_WAIT1()  asm volatile("cp.async.wait_group 1;" ::: "memory")

#define MMA(C, A, B)                                                           \
    asm volatile(                                                              \
        "mma.sync.aligned.m16n8k16.row.col.f32.bf16.bf16.f32 "                 \
        "{%0,%1,%2,%3}, {%4,%5,%6,%7}, {%8,%9}, {%0,%1,%2,%3};"                \
        : "+f"((C)[0]), "+f"((C)[1]), "+f"((C)[2]), "+f"((C)[3])               \
        : "r"((A)[0]), "r"((A)[1]), "r"((A)[2]), "r"((A)[3]),                  \
          "r"((B)[0]), "r"((B)[1]))

// ---------------------------------------------------------------------------
// Complex GEMM: O[b,i] = sum_k U[i,k] * S[b,k]
// S: 4 packed bf16 arrays (rH, rL, iH, iL) -> cp.async 3-stage ring.
// U: fp32, register-prefetched + cvt into 2-stage ring.
// O: 4 packed bf16 arrays (epilogue hi/lo split).
// CTA 64x64, 4 warps 2x2 (warp tile 32x32), grid (64,4)=256 CTAs, 2 CTAs/SM.
// ---------------------------------------------------------------------------
template <bool CPLX>
__global__ void __launch_bounds__(128, 2)
cgemm_mma(const float* __restrict__ Ur, const float* __restrict__ Ui,
          const __nv_bfloat16* __restrict__ S, __nv_bfloat16* __restrict__ O) {
    extern __shared__ __align__(16) __nv_bfloat16 sm[];
    char* smc = reinterpret_cast<char*>(sm);

    const int tid = threadIdx.x;
    const int wid = tid >> 5;
    const int lane = tid & 31;
    const int ibase = blockIdx.x * 64;
    const int bbase = blockIdx.y * 64;

    const __nv_bfloat16* gSrH = S;
    const __nv_bfloat16* gSrL = S + PKN;
    const __nv_bfloat16* gSiH = S + 2 * PKN;
    const __nv_bfloat16* gSiL = S + 3 * PKN;
    __nv_bfloat16* gOrH = O;
    __nv_bfloat16* gOrL = O + PKN;
    __nv_bfloat16* gOiH = O + 2 * PKN;
    __nv_bfloat16* gOiL = O + 3 * PKN;

    // S cp.async mapping: 2 threads per row (16B halves)
    const int crow = tid >> 1;
    const int chalf = tid & 1;
    const size_t cgoff = (size_t)(bbase + crow) * DD + chalf * 8;
    const uint32_t csm = crow * SROWB + chalf * 16;

    // U loader mapping
    const int arow = tid >> 2;            // 0..31
    const int akp = (tid & 3) << 2;       // 0,4,8,12
    const float* pUr0 = Ur + (size_t)(ibase + arow) * DD + akp;
    const float* pUr1 = Ur + (size_t)(ibase + arow + 32) * DD + akp;
    const float* pUi0 = Ui + (size_t)(ibase + arow) * DD + akp;
    const float* pUi1 = Ui + (size_t)(ibase + arow + 32) * DD + akp;

    // compute mapping
    const int warp_m = wid & 1;
    const int warp_n = wid >> 1;
    const int lrow = lane >> 2;
    const int lcol2 = (lane & 3) << 1;

    const uint32_t aLane = (uint32_t)((lane & 15) * SROWB + (lane >> 4) * 16);
    const uint32_t bLane = (uint32_t)((((lane >> 4) << 3) + (lane & 7)) * SROWB +
                                      ((lane >> 3) & 1) * 16);
    const uint32_t smbase = smem_u32(sm);

    float cR[2][4][4], cI[2][4][4];
#pragma unroll
    for (int m = 0; m < 2; ++m)
#pragma unroll
        for (int n = 0; n < 4; ++n)
#pragma unroll
            for (int r = 0; r < 4; ++r) { cR[m][n][r] = 0.f; cI[m][n][r] = 0.f; }

    auto stageS = [&](int st, int kbase) {
        const uint32_t d = smbase + st * STAGE_BYTES + csm;
        const size_t g = cgoff + kbase;
        cpasync16(d + TB_H0, gSrH + g);
        cpasync16(d + TB_L0, gSrL + g);
        if (CPLX) {
            cpasync16(d + TB_H1, gSiH + g);
            cpasync16(d + TB_L1, gSiL + g);
        }
    };
    auto stageU = [&](int buf, const float4* v) {
        char* B = smc + U_BASE + buf * STAGE_BYTES;
        uint32_t h0, l0, h1, l1;
        const int ro0 = arow * SROWB + akp * 2;
        const int ro1 = (arow + 32) * SROWB + akp * 2;
        cvt_hilo2(v[0].x, v[0].y, h0, l0); cvt_hilo2(v[0].z, v[0].w, h1, l1);
        *reinterpret_cast<uint2*>(B + TB_H0 + ro0) = make_uint2(h0, h1);
        *reinterpret_cast<uint2*>(B + TB_L0 + ro0) = make_uint2(l0, l1);
        cvt_hilo2(v[1].x, v[1].y, h0, l0); cvt_hilo2(v[1].z, v[1].w, h1, l1);
        *reinterpret_cast<uint2*>(B + TB_H0 + ro1) = make_uint2(h0, h1);
        *reinterpret_cast<uint2*>(B + TB_L0 + ro1) = make_uint2(l0, l1);
        cvt_hilo2(v[2].x, v[2].y, h0, l0); cvt_hilo2(v[2].z, v[2].w, h1, l1);
        *reinterpret_cast<uint2*>(B + TB_H1 + ro0) = make_uint2(h0, h1);
        *reinterpret_cast<uint2*>(B + TB_L1 + ro0) = make_uint2(l0, l1);
        cvt_hilo2(v[3].x, v[3].y, h0, l0); cvt_hilo2(v[3].z, v[3].w, h1, l1);
        *reinterpret_cast<uint2*>(B + TB_H1 + ro1) = make_uint2(h0, h1);
        *reinterpret_cast<uint2*>(B + TB_L1 + ro1) = make_uint2(l0, l1);
    };
    auto prefU = [&](float4* v, int off) {
        v[0] = *reinterpret_cast<const float4*>(pUr0 + off);
        v[1] = *reinterpret_cast<const float4*>(pUr1 + off);
        v[2] = *reinterpret_cast<const float4*>(pUi0 + off);
        v[3] = *reinterpret_cast<const float4*>(pUi1 + off);
    };

    // prologue: S chunks 0,1 in flight; U chunk 0 staged; U chunk 1 in regs
    float4 v[4];
    stageS(0, 0);
    CP_COMMIT();
    stageS(1, KC);
    CP_COMMIT();
    prefU(v, 0);
    stageU(0, v);
    prefU(v, KC);
    CP_WAIT0();
    __syncthreads();

    int s_stage = 0;  // ring stage holding chunk c
#pragma unroll 1
    for (int c = 0; c < NCHUNK; ++c) {
        const uint32_t base_s = smbase + (uint32_t)(s_stage * STAGE_BYTES);
        const uint32_t base_u = smbase + (uint32_t)(U_BASE + (c & 1) * STAGE_BYTES);

        // ---- 1) fragments for chunk c ----
        uint32_t aSrH[2][4], aSrL[2][4], aSiH[2][4], aSiL[2][4];
#pragma unroll
        for (int m = 0; m < 2; ++m) {
            const uint32_t am = base_s + aLane + (uint32_t)((warp_m * 32 + m * 16) * SROWB);
            ldm4(aSrH[m], am + TB_H0);
            ldm4(aSrL[m], am + TB_L0);
            if (CPLX) {
                ldm4(aSiH[m], am + TB_H1);
                ldm4(aSiL[m], am + TB_L1);
            }
        }
        uint32_t bUrH[2][4], bUrL[2][4], bUiH[2][4], bUiL[2][4];
#pragma unroll
        for (int np = 0; np < 2; ++np) {
            const uint32_t bm = base_u + bLane + (uint32_t)((warp_n * 32 + np * 16) * SROWB);
            ldm4(bUrH[np], bm + TB_H0);
            ldm4(bUrL[np], bm + TB_L0);
            ldm4(bUiH[np], bm + TB_H1);
            ldm4(bUiL[np], bm + TB_L1);
        }

        // ---- 2) async S for chunk c+2; stage U c+1; prefetch U c+2 ----
        int ns = s_stage + 2; if (ns >= 3) ns -= 3;
        if (c + 2 < NCHUNK) stageS(ns, (c + 2) * KC);
        CP_COMMIT();  // always commit (keeps wait_group accounting exact)
        if (c + 1 < NCHUNK) stageU((c + 1) & 1, v);
        if (c + 2 < NCHUNK) prefU(v, (c + 2) * KC);

        // ---- 3) MMA burst, round-robin interleaved across 4 accumulators ----
        // Per-accumulator addition order identical to R10 (hh, lh, hl, then
        // Si-hh, Si-lh, Si-hl) -> bit-identical results; only the global
        // instruction interleave changes (breaks same-acc RAW chains).
#pragma unroll
        for (int m = 0; m < 2; ++m) {
            uint32_t aSiHn[4], aSiLn[4];
            if (CPLX) {
#pragma unroll
                for (int r = 0; r < 4; ++r) {
                    aSiHn[r] = aSiH[m][r] ^ 0x80008000u;
                    aSiLn[r] = aSiL[m][r] ^ 0x80008000u;
                }
            }
#pragma unroll
            for (int np = 0; np < 2; ++np) {
                const int n0 = np * 2, n1 = np * 2 + 1;
                // term 1: SrH x U_hi
                MMA(cR[m][n0], aSrH[m], bUrH[np] + 0);
                MMA(cI[m][n0], aSrH[m], bUiH[np] + 0);
                MMA(cR[m][n1], aSrH[m], bUrH[np] + 2);
                MMA(cI[m][n1], aSrH[m], bUiH[np] + 2);
                // term 2: SrL x U_hi
                MMA(cR[m][n0], aSrL[m], bUrH[np] + 0);
                MMA(cI[m][n0], aSrL[m], bUiH[np] + 0);
                MMA(cR[m][n1], aSrL[m], bUrH[np] + 2);
                MMA(cI[m][n1], aSrL[m], bUiH[np] + 2);
                // term 3: SrH x U_lo
                MMA(cR[m][n0], aSrH[m], bUrL[np] + 0);
                MMA(cI[m][n0], aSrH[m], bUiL[np] + 0);
                MMA(cR[m][n1], aSrH[m], bUrL[np] + 2);
                MMA(cI[m][n1], aSrH[m], bUiL[np] + 2);
                if (CPLX) {
                    // term 4: SiH x U_hi (R negated)
                    MMA(cR[m][n0], aSiHn, bUiH[np] + 0);
                    MMA(cI[m][n0], aSiH[m], bUrH[np] + 0);
                    MMA(cR[m][n1], aSiHn, bUiH[np] + 2);
                    MMA(cI[m][n1], aSiH[m], bUrH[np] + 2);
                    // term 5: SiL x U_hi
                    MMA(cR[m][n0], aSiLn, bUiH[np] + 0);
                    MMA(cI[m][n0], aSiL[m], bUrH[np] + 0);
                    MMA(cR[m][n1], aSiLn, bUiH[np] + 2);
                    MMA(cI[m][n1], aSiL[m], bUrH[np] + 2);
                    // term 6: SiH x U_lo
                    MMA(cR[m][n0], aSiHn, bUiL[np] + 0);
                    MMA(cI[m][n0], aSiH[m], bUrL[np] + 0);
                    MMA(cR[m][n1], aSiHn, bUiL[np] + 2);
                    MMA(cI[m][n1], aSiH[m], bUrL[np] + 2);
                }
            }
        }

        // chunk c+1's S group must drain; c+2's may remain in flight
        CP_WAIT1();
        __syncthreads();
        if (++s_stage == 3) s_stage = 0;
    }

    // epilogue: hi/lo split in registers, packed bf16 global stores
#pragma unroll
    for (int m = 0; m < 2; ++m) {
#pragma unroll
        for (int n = 0; n < 4; ++n) {
            const int brow = bbase + warp_m * 32 + m * 16 + lrow;
            const int icol = ibase + warp_n * 32 + n * 8 + lcol2;
            uint32_t hi, lo;
            cvt_hilo2(cR[m][n][0], cR[m][n][1], hi, lo);
            *reinterpret_cast<uint32_t*>(gOrH + (size_t)brow * DD + icol) = hi;
            *reinterpret_cast<uint32_t*>(gOrL + (size_t)brow * DD + icol) = lo;
            cvt_hilo2(cR[m][n][2], cR[m][n][3], hi, lo);
            *reinterpret_cast<uint32_t*>(gOrH + (size_t)(brow + 8) * DD + icol) = hi;
            *reinterpret_cast<uint32_t*>(gOrL + (size_t)(brow + 8) * DD + icol) = lo;
            cvt_hilo2(cI[m][n][0], cI[m][n][1], hi, lo);
            *reinterpret_cast<uint32_t*>(gOiH + (size_t)brow * DD + icol) = hi;
            *reinterpret_cast<uint32_t*>(gOiL + (size_t)brow * DD + icol) = lo;
            cvt_hilo2(cI[m][n][2], cI[m][n][3], hi, lo);
            *reinterpret_cast<uint32_t*>(gOiH + (size_t)(brow + 8) * DD + icol) = hi;
            *reinterpret_cast<uint32_t*>(gOiL + (size_t)(brow + 8) * DD + icol) = lo;
        }
    }
}

// ---------------------------------------------------------------------------
__global__ void normalize_kernel(const float* __restrict__ x, __nv_bfloat16* __restrict__ O) {
    const int b = blockIdx.x;
    const float4* xv = reinterpret_cast<const float4*>(x + (size_t)b * DD);
    float ss = 0.f;
#pragma unroll 4
    for (int i = threadIdx.x; i < DD / 4; i += blockDim.x) {
        float4 v = xv[i];
        ss += v.x * v.x + v.y * v.y + v.z * v.z + v.w * v.w;
    }
    __shared__ float red[256];
    red[threadIdx.x] = ss;
    __syncthreads();
    for (int s = 128; s > 0; s >>= 1) {
        if (threadIdx.x < s) red[threadIdx.x] += red[threadIdx.x + s];
        __syncthreads();
    }
    const float inv = rsqrtf(red[0]);
    __nv_bfloat16* gH = O;
    __nv_bfloat16* gL = O + PKN;
    for (int i = threadIdx.x; i < DD / 4; i += blockDim.x) {
        float4 v = xv[i];
        v.x *= inv; v.y *= inv; v.z *= inv; v.w *= inv;
        uint32_t h0, l0, h1, l1;
        cvt_hilo2(v.x, v.y, h0, l0);
        cvt_hilo2(v.z, v.w, h1, l1);
        *reinterpret_cast<uint2*>(gH + (size_t)b * DD + i * 4) = make_uint2(h0, h1);
        *reinterpret_cast<uint2*>(gL + (size_t)b * DD + i * 4) = make_uint2(l0, l1);
    }
}

__global__ void perm_kernel(const __nv_bfloat16* __restrict__ in,
                            __nv_bfloat16* __restrict__ out) {
    const int idx = blockIdx.x * blockDim.x + threadIdx.x;
    const int b = idx >> 12;
    const int j = idx & (DD - 1);
    int m = j;
#pragma unroll
    for (int i = NW - 1; i >= 0; --i) {
        const int cc = NW - 1 - i;
        const int t = NW - 1 - ((i + 1) % NW);
        m ^= ((m >> cc) & 1) << t;
    }
    const size_t src = ((size_t)b << 12) + m;
    out[idx] = in[src];
    out[idx + PKN] = in[src + PKN];
    out[idx + 2 * PKN] = in[src + 2 * PKN];
    out[idx + 3 * PKN] = in[src + 3 * PKN];
}

__global__ void abs_kernel(const __nv_bfloat16* __restrict__ S, float* __restrict__ out) {
    const int idx = blockIdx.x * blockDim.x + threadIdx.x;
    const float r = __bfloat162float(S[idx]) + __bfloat162float(S[idx + PKN]);
    const float i = __bfloat162float(S[idx + 2 * PKN]) + __bfloat162float(S[idx + 3 * PKN]);
    out[idx] = sqrtf(r * r + i * i);
}

// ---------------------------------------------------------------------------
extern "C" void kernel_launch(void* const* d_in, const int* in_sizes, int n_in,
                              void* d_out, int out_size) {
    const float* x   = (const float*)d_in[0];
    const float* u0r = (const float*)d_in[1];
    const float* u0i = (const float*)d_in[2];
    const float* u1r = (const float*)d_in[3];
    const float* u1i = (const float*)d_in[4];
    const float* u2r = (const float*)d_in[5];
    const float* u2i = (const float*)d_in[6];
    const float* u3r = (const float*)d_in[7];
    const float* u3i = (const float*)d_in[8];
    float* out = (float*)d_out;

    cudaFuncSetAttribute(cgemm_mma<true>, cudaFuncAttributeMaxDynamicSharedMemorySize,
                         SMEM_BYTES);
    cudaFuncSetAttribute(cgemm_mma<false>, cudaFuncAttributeMaxDynamicSharedMemorySize,
                         SMEM_BYTES);

    __nv_bfloat16* pk;
    cudaGetSymbolAddress((void**)&pk, g_pk);
    __nv_bfloat16* pk0 = pk;
    __nv_bfloat16* pk1 = pk + 4 * PKN;

    const dim3 gg(DD / 64, BB / 64);  // (64, 4) = 256 CTAs
    const int elems = BB * DD;

    normalize_kernel<<<BB, 256>>>(x, pk0);
    cgemm_mma<false><<<gg, 128, SMEM_BYTES>>>(u0r, u0i, pk0, pk1);
    perm_kernel<<<elems / 256, 256>>>(pk1, pk0);
    cgemm_mma<true><<<gg, 128, SMEM_BYTES>>>(u1r, u1i, pk0, pk1);
    cgemm_mma<true><<<gg, 128, SMEM_BYTES>>>(u2r, u2i, pk1, pk0);
    perm_kernel<<<elems / 256, 256>>>(pk0, pk1);
    cgemm_mma<true><<<gg, 128, SMEM_BYTES>>>(u3r, u3i, pk1, pk0);
    abs_kernel<<<elems / 256, 256>>>(pk0, out);
}